// round 4
// baseline (speedup 1.0000x reference)
#include <cuda_runtime.h>
#include <cuda_bf16.h>

#define CW    32      // context window
#define DDIM  512     // embedding dim
#define NTHR  128     // threads per block: each owns one float4 slice of D

// Dynamic smem layout (floats):
//   s_ctx  [CW * DDIM]   : cached context rows (64 KB)
//   s_part [CW * 4]      : per-warp distance partials
//   s_w    [CW]          : weights
//   s_misc [4]           : [0] = 1/(sum+1e-8)
//   s_idx  [CW] (ints)   : context indices for this row
#define SMEM_FLOATS (CW*DDIM + CW*4 + CW + 4)
#define SMEM_BYTES  (SMEM_FLOATS*4 + CW*4)

__global__ __launch_bounds__(NTHR, 3)
void kre_kernel(const int* __restrict__ context,
                const int* __restrict__ center,
                const float* __restrict__ W,
                float* __restrict__ out)
{
    extern __shared__ float s[];
    float* s_ctx  = s;
    float* s_part = s + CW*DDIM;
    float* s_w    = s_part + CW*4;
    float* s_misc = s_w + CW;
    int*   s_idx  = (int*)(s_misc + 4);

    const int b    = blockIdx.x;
    const int tid  = threadIdx.x;
    const int lane = tid & 31;
    const int warp = tid >> 5;

    if (tid < CW) s_idx[tid] = context[b*CW + tid];
    __syncthreads();

    const int cen_idx = __ldg(&center[b]);
    const float4 cen4 = *(const float4*)(W + (size_t)cen_idx*DDIM + tid*4);

    float4* s_ctx4 = (float4*)s_ctx;

    // Phase 1: gather context rows (one L2 read each), cache in SMEM,
    // accumulate squared-distance partials with warp shuffles.
    #pragma unroll 4
    for (int c = 0; c < CW; ++c) {
        const int idx = s_idx[c];
        float4 v = *(const float4*)(W + (size_t)idx*DDIM + tid*4);
        s_ctx4[c*NTHR + tid] = v;
        float dx = v.x - cen4.x;
        float dy = v.y - cen4.y;
        float dz = v.z - cen4.z;
        float dw = v.w - cen4.w;
        float d = dx*dx + dy*dy + dz*dz + dw*dw;
        d += __shfl_xor_sync(0xffffffffu, d, 16);
        d += __shfl_xor_sync(0xffffffffu, d, 8);
        d += __shfl_xor_sync(0xffffffffu, d, 4);
        d += __shfl_xor_sync(0xffffffffu, d, 2);
        d += __shfl_xor_sync(0xffffffffu, d, 1);
        if (lane == 0) s_part[c*4 + warp] = d;
    }
    __syncthreads();

    // Phase 2: warp 0 computes the 32 weights ONCE (avoid 128x redundant MUFU)
    if (tid < CW) {
        float dsq = s_part[tid*4+0] + s_part[tid*4+1]
                  + s_part[tid*4+2] + s_part[tid*4+3];
        float w = expf(-0.5f * dsq);   // SIGMA = 1
        s_w[tid] = w;
        float ssum = w;
        ssum += __shfl_xor_sync(0xffffffffu, ssum, 16);
        ssum += __shfl_xor_sync(0xffffffffu, ssum, 8);
        ssum += __shfl_xor_sync(0xffffffffu, ssum, 4);
        ssum += __shfl_xor_sync(0xffffffffu, ssum, 2);
        ssum += __shfl_xor_sync(0xffffffffu, ssum, 1);
        if (tid == 0) s_misc[0] = 1.0f / (ssum + 1e-8f);
    }
    __syncthreads();

    // Phase 3: weighted sum from SMEM (no second L2 pass)
    const float inv = s_misc[0];
    float4 acc = make_float4(0.f, 0.f, 0.f, 0.f);
    #pragma unroll 8
    for (int c = 0; c < CW; ++c) {
        const float wc = s_w[c] * inv;
        const float4 v = s_ctx4[c*NTHR + tid];
        acc.x = fmaf(wc, v.x, acc.x);
        acc.y = fmaf(wc, v.y, acc.y);
        acc.z = fmaf(wc, v.z, acc.z);
        acc.w = fmaf(wc, v.w, acc.w);
    }
    *(float4*)(out + (size_t)b*DDIM + tid*4) = acc;
}

extern "C" void kernel_launch(void* const* d_in, const int* in_sizes, int n_in,
                              void* d_out, int out_size)
{
    const int*   context = (const int*)d_in[0];   // [B, C] int32
    const int*   center  = (const int*)d_in[1];   // [B]    int32
    const float* W       = (const float*)d_in[2]; // [V, D] float32
    float*       out     = (float*)d_out;         // [B, D] float32

    const int B = in_sizes[1];                    // 8192

    cudaFuncSetAttribute(kre_kernel,
                         cudaFuncAttributeMaxDynamicSharedMemorySize,
                         SMEM_BYTES);

    kre_kernel<<<B, NTHR, SMEM_BYTES>>>(context, center, W, out);
}

// round 5
// speedup vs baseline: 4.4174x; 4.4174x over previous
#include <cuda_runtime.h>
#include <cuda_bf16.h>

#define CW    32            // context window
#define DDIM  512           // embedding dim
#define NTHR  128           // 4 warps per CTA, one CTA per batch row
#define NW    4             // warps per CTA
#define CPW   (CW / NW)     // context rows per warp = 8

// Lane l owns dims { i*128 + l*4 .. +4 } for i in 0..3  (coalesced, conflict-free)

__global__ __launch_bounds__(NTHR, 6)
void kre_kernel(const int* __restrict__ context,
                const int* __restrict__ center,
                const float* __restrict__ W,
                float* __restrict__ out)
{
    __shared__ float s_acc[NW * DDIM];   // per-warp partial outputs (8 KB)
    __shared__ float s_wsum[NW];
    __shared__ int   s_idx[CW];

    const int b    = blockIdx.x;
    const int tid  = threadIdx.x;
    const int lane = tid & 31;
    const int warp = tid >> 5;

    if (tid < CW) s_idx[tid] = context[b * CW + tid];
    __syncthreads();

    // Center row slice for this lane (broadcast read of center[b])
    const size_t cen_base = (size_t)center[b] * DDIM;
    float4 cen[4];
    #pragma unroll
    for (int i = 0; i < 4; ++i)
        cen[i] = *(const float4*)(W + cen_base + i * 128 + lane * 4);

    float4 acc[4];
    #pragma unroll
    for (int i = 0; i < 4; ++i) acc[i] = make_float4(0.f, 0.f, 0.f, 0.f);
    float wsum = 0.f;

    // Each warp: 8 context rows, fully self-contained (dsq reduce in-warp,
    // weight broadcast for free, accumulate in registers — ONE pass over W).
    #pragma unroll
    for (int cc = 0; cc < CPW; ++cc) {
        const size_t base = (size_t)s_idx[warp * CPW + cc] * DDIM;
        float4 v[4];
        #pragma unroll
        for (int i = 0; i < 4; ++i)
            v[i] = *(const float4*)(W + base + i * 128 + lane * 4);

        float d = 0.f;
        #pragma unroll
        for (int i = 0; i < 4; ++i) {
            float dx = v[i].x - cen[i].x;
            float dy = v[i].y - cen[i].y;
            float dz = v[i].z - cen[i].z;
            float dw = v[i].w - cen[i].w;
            d = fmaf(dx, dx, d);
            d = fmaf(dy, dy, d);
            d = fmaf(dz, dz, d);
            d = fmaf(dw, dw, d);
        }
        d += __shfl_xor_sync(0xffffffffu, d, 16);
        d += __shfl_xor_sync(0xffffffffu, d, 8);
        d += __shfl_xor_sync(0xffffffffu, d, 4);
        d += __shfl_xor_sync(0xffffffffu, d, 2);
        d += __shfl_xor_sync(0xffffffffu, d, 1);

        const float wgt = __expf(-0.5f * d);   // SIGMA = 1; exact 1.0 at d==0
        wsum += wgt;

        #pragma unroll
        for (int i = 0; i < 4; ++i) {
            acc[i].x = fmaf(wgt, v[i].x, acc[i].x);
            acc[i].y = fmaf(wgt, v[i].y, acc[i].y);
            acc[i].z = fmaf(wgt, v[i].z, acc[i].z);
            acc[i].w = fmaf(wgt, v[i].w, acc[i].w);
        }
    }

    // Spill per-warp partials (lane stride 16 B -> conflict-free)
    #pragma unroll
    for (int i = 0; i < 4; ++i)
        *(float4*)(s_acc + warp * DDIM + i * 128 + lane * 4) = acc[i];
    if (lane == 0) s_wsum[warp] = wsum;   // wgt broadcast => wsum lane-uniform
    __syncthreads();

    // Combine 4 warp partials; normalize once at the end (same math as ref)
    const float inv = 1.0f / (s_wsum[0] + s_wsum[1] + s_wsum[2] + s_wsum[3] + 1e-8f);

    float4 r = make_float4(0.f, 0.f, 0.f, 0.f);
    #pragma unroll
    for (int w = 0; w < NW; ++w) {
        const float4 p = *(const float4*)(s_acc + w * DDIM + tid * 4);
        r.x += p.x; r.y += p.y; r.z += p.z; r.w += p.w;
    }
    r.x *= inv; r.y *= inv; r.z *= inv; r.w *= inv;
    *(float4*)(out + (size_t)b * DDIM + tid * 4) = r;
}

extern "C" void kernel_launch(void* const* d_in, const int* in_sizes, int n_in,
                              void* d_out, int out_size)
{
    const int*   context = (const int*)d_in[0];   // [B, C] int32
    const int*   center  = (const int*)d_in[1];   // [B]    int32
    const float* W       = (const float*)d_in[2]; // [V, D] float32
    float*       out     = (float*)d_out;         // [B, D] float32

    const int B = in_sizes[1];                    // 8192

    kre_kernel<<<B, NTHR>>>(context, center, W, out);
}